// round 14
// baseline (speedup 1.0000x reference)
#include <cuda_runtime.h>
#include <cuda_bf16.h>
#include <math.h>
#include <stdint.h>

// Problem constants
#define BB 32
#define SS 744
#define SP 768          // padded sequence for mma attention
#define DD 512
#define HH 8
#define HD 64
#define LL 4
#define MM (BB*SS)      // 23808 = 128*186
#define FF (4*DD)       // 2048

__device__ __forceinline__ uint32_t smem_u32(const void* p) {
    uint32_t a;
    asm("{ .reg .u64 t; cvta.to.shared.u64 t, %1; cvt.u32.u64 %0, t; }" : "=r"(a) : "l"(p));
    return a;
}
__device__ __forceinline__ void cp16(uint32_t dst, const void* src) {
    asm volatile("cp.async.cg.shared.global [%0], [%1], 16;" :: "r"(dst), "l"(src) : "memory");
}
#define CP_COMMIT() asm volatile("cp.async.commit_group;" ::: "memory")
#define CP_WAIT1()  asm volatile("cp.async.wait_group 1;" ::: "memory")
#define CP_WAIT0()  asm volatile("cp.async.wait_group 0;" ::: "memory")

// pack two f32 -> bf16x2 (first arg in bits 0-15)
__device__ __forceinline__ uint32_t pk2(float lo, float hi) {
    uint32_t r;
    asm("cvt.rn.bf16x2.f32 %0, %1, %2;" : "=r"(r) : "f"(hi), "f"(lo));
    return r;
}

#define MMA_BF16(c, a, b) \
    asm volatile("mma.sync.aligned.m16n8k16.row.col.f32.bf16.bf16.f32 " \
        "{%0,%1,%2,%3}, {%4,%5,%6,%7}, {%8,%9}, {%0,%1,%2,%3};" \
        : "+f"((c)[0]), "+f"((c)[1]), "+f"((c)[2]), "+f"((c)[3]) \
        : "r"((a)[0]), "r"((a)[1]), "r"((a)[2]), "r"((a)[3]), \
          "r"((b)[0]), "r"((b)[1]))

#define LDMATRIX_X4(r, addr) \
    asm volatile("ldmatrix.sync.aligned.m8n8.x4.shared.b16 {%0,%1,%2,%3}, [%4];" \
        : "=r"((r)[0]), "=r"((r)[1]), "=r"((r)[2]), "=r"((r)[3]) : "r"(addr))

#define LDMATRIX_X4T(r, addr) \
    asm volatile("ldmatrix.sync.aligned.m8n8.x4.trans.shared.b16 {%0,%1,%2,%3}, [%4];" \
        : "=r"((r)[0]), "=r"((r)[1]), "=r"((r)[2]), "=r"((r)[3]) : "r"(addr))

#define LDMATRIX_X2(r, addr) \
    asm volatile("ldmatrix.sync.aligned.m8n8.x2.shared.b16 {%0,%1}, [%2];" \
        : "=r"((r)[0]), "=r"((r)[1]) : "r"(addr))

// ---------------------------------------------------------------------------
// Scratch (device globals)
// ---------------------------------------------------------------------------
__device__ float g_t [MM*DD];
// split-bf16 residual stream h
__device__ __nv_bfloat16 g_hh [MM*DD];
__device__ __nv_bfloat16 g_hl [MM*DD];
// bf16 attention operands, padded to SP rows, layout [B*H, SP, HD]
__device__ __nv_bfloat16 g_qh[(size_t)BB*HH*SP*HD];   // pre-scaled by 0.125
__device__ __nv_bfloat16 g_kh[(size_t)BB*HH*SP*HD];
__device__ __nv_bfloat16 g_vh[(size_t)BB*HH*SP*HD];
__device__ __nv_bfloat16 g_vl[(size_t)BB*HH*SP*HD];
// split-bf16 activations (hi, lo)
__device__ __nv_bfloat16 g_oh [MM*DD];
__device__ __nv_bfloat16 g_ol [MM*DD];
__device__ __nv_bfloat16 g_n1h[MM*DD];
__device__ __nv_bfloat16 g_n1l[MM*DD];
__device__ __nv_bfloat16 g_ffh[(size_t)MM*FF];
__device__ __nv_bfloat16 g_ffl[(size_t)MM*FF];
// split-bf16 weights
__device__ __nv_bfloat16 g_woh[LL*DD*DD];
__device__ __nv_bfloat16 g_wol[LL*DD*DD];
__device__ __nv_bfloat16 g_w1h[LL*FF*DD];
__device__ __nv_bfloat16 g_w1l[LL*FF*DD];
__device__ __nv_bfloat16 g_w2h[(size_t)LL*DD*FF];
__device__ __nv_bfloat16 g_w2l[(size_t)LL*DD*FF];

// ---------------------------------------------------------------------------
// Pack all big weights fp32 -> split-bf16 in ONE launch
// ---------------------------------------------------------------------------
#define PN1 (LL*DD*DD)    // 1048576
#define PN2 (LL*FF*DD)    // 4194304
#define PTOT (PN1 + 2*PN2)

__global__ void pack_all_kernel(const float* __restrict__ Wo,
                                const float* __restrict__ W1,
                                const float* __restrict__ W2,
                                __nv_bfloat16* __restrict__ woh, __nv_bfloat16* __restrict__ wol,
                                __nv_bfloat16* __restrict__ w1h, __nv_bfloat16* __restrict__ w1l,
                                __nv_bfloat16* __restrict__ w2h, __nv_bfloat16* __restrict__ w2l)
{
    int i = blockIdx.x * 256 + threadIdx.x;
    const float* src; __nv_bfloat16 *dh, *dl; int j;
    if (i < PN1)            { src = Wo; dh = woh; dl = wol; j = i; }
    else if (i < PN1 + PN2) { src = W1; dh = w1h; dl = w1l; j = i - PN1; }
    else if (i < PTOT)      { src = W2; dh = w2h; dl = w2l; j = i - PN1 - PN2; }
    else return;
    float v = src[j];
    __nv_bfloat16 hb = __float2bfloat16(v);
    dh[j] = hb;
    dl[j] = __float2bfloat16(v - __bfloat162float(hb));
}

// ---------------------------------------------------------------------------
// QKV v3: mma-based per-head projection, optional fused embedding (layer 0).
// grid = (B*H, SP/64); block = 128 (4 warps, 16 s-rows each).
// Weights converted fp32 -> split-bf16 in-kernel (L2-resident).
// Q,K: single bf16 product. V: 3-product split (accuracy-critical).
// ---------------------------------------------------------------------------
#define QK_ROWB 144                    // 72 halves per smem row
#define QK_MAT  9216                   // 64 x 72 halves
#define QK_SMEM (6*QK_MAT)             // Xh|Xl|Wq|Wk|Wvh|Wvl = 55296

template<bool EMBED>
__global__ __launch_bounds__(128) void qkv3_kernel(
        const __nv_bfloat16* __restrict__ hh, const __nv_bfloat16* __restrict__ hl,
        const int* __restrict__ xt, const float* __restrict__ emb,
        const float* __restrict__ pe,
        const float* __restrict__ Wq, const float* __restrict__ Wk,
        const float* __restrict__ Wv,
        __nv_bfloat16* __restrict__ qh, __nv_bfloat16* __restrict__ kh,
        __nv_bfloat16* __restrict__ vh, __nv_bfloat16* __restrict__ vl,
        __nv_bfloat16* __restrict__ ohh, __nv_bfloat16* __restrict__ ohl)
{
    extern __shared__ char qsm[];
    const uint32_t sb = smem_u32(qsm);
    const int bh  = blockIdx.x;
    const int qt  = blockIdx.y;
    const int b   = bh >> 3;
    const int hd0 = (bh & 7) * HD;
    const int tid = threadIdx.x;
    const int lane = tid & 31;
    const int w    = tid >> 5;

    // ---- stage weights: fp32 -> bf16 (Wq/Wk hi; Wv split) ----
#pragma unroll
    for (int i = 0; i < 8; i++) {
        int idx = tid + i * 128;               // 0..1023 float4s
        int row = idx >> 4, d4 = (idx & 15) * 4;
        uint32_t off = (uint32_t)(row * QK_ROWB + d4 * 2);
        float4 aq = *(const float4*)(Wq + row * HD + d4);
        *(uint2*)(qsm + 2*QK_MAT + off) = make_uint2(pk2(aq.x, aq.y), pk2(aq.z, aq.w));
        float4 ak = *(const float4*)(Wk + row * HD + d4);
        *(uint2*)(qsm + 3*QK_MAT + off) = make_uint2(pk2(ak.x, ak.y), pk2(ak.z, ak.w));
        float4 av = *(const float4*)(Wv + row * HD + d4);
        float hx = __bfloat162float(__float2bfloat16(av.x));
        float hy = __bfloat162float(__float2bfloat16(av.y));
        float hz = __bfloat162float(__float2bfloat16(av.z));
        float hw = __bfloat162float(__float2bfloat16(av.w));
        *(uint2*)(qsm + 4*QK_MAT + off) = make_uint2(pk2(hx, hy), pk2(hz, hw));
        *(uint2*)(qsm + 5*QK_MAT + off) =
            make_uint2(pk2(av.x - hx, av.y - hy), pk2(av.z - hz, av.w - hw));
    }

    // ---- stage X tile (split) ----
    if (EMBED) {
#pragma unroll
        for (int i = 0; i < 32; i++) {
            int idx = tid + i * 128;           // 0..4095
            int r = idx >> 6, d = idx & 63;
            int s = qt * 64 + r;
            int sc = s < SS ? s : SS - 1;
            int tok = xt[b * SS + sc];
            float v = emb[(size_t)tok * DD + hd0 + d] * 22.627416997969522f
                    + pe[(size_t)sc * DD + hd0 + d];
            __nv_bfloat16 hb = __float2bfloat16(v);
            __nv_bfloat16 lb = __float2bfloat16(v - __bfloat162float(hb));
            *(__nv_bfloat16*)(qsm + 0*QK_MAT + r * QK_ROWB + d * 2) = hb;
            *(__nv_bfloat16*)(qsm + 1*QK_MAT + r * QK_ROWB + d * 2) = lb;
            if (s < SS) {
                size_t gi = (size_t)(b * SS + s) * DD + hd0 + d;
                ohh[gi] = hb;
                ohl[gi] = lb;
            }
        }
    } else {
#pragma unroll
        for (int i = 0; i < 4; i++) {
            int idx = tid + i * 128;           // 0..511 uint4s
            int r = idx >> 3, c8 = (idx & 7) * 8;
            int s = qt * 64 + r;
            int sc = s < SS ? s : SS - 1;
            size_t gi = (size_t)(b * SS + sc) * DD + hd0 + c8;
            *(uint4*)(qsm + 0*QK_MAT + r * QK_ROWB + c8 * 2) = *(const uint4*)(hh + gi);
            *(uint4*)(qsm + 1*QK_MAT + r * QK_ROWB + c8 * 2) = *(const uint4*)(hl + gi);
        }
    }
    __syncthreads();

    // ---- fragments ----
    const int l16   = lane & 15;
    const int arow  = l16;
    const int acsel = (lane >> 4) * 8;

    uint32_t Ah[4][4], Al[4][4];
#pragma unroll
    for (int kk = 0; kk < 4; kk++) {
        uint32_t r = (uint32_t)((w * 16 + arow) * QK_ROWB + (kk * 16 + acsel) * 2);
        LDMATRIX_X4(Ah[kk], sb + 0*QK_MAT + r);
        LDMATRIX_X4(Al[kk], sb + 1*QK_MAT + r);
    }

    float qa[8][4] = {}, ka[8][4] = {}, va[8][4] = {};
#pragma unroll
    for (int kk = 0; kk < 4; kk++) {
        uint32_t bf[8][2];
        // Q
#pragma unroll
        for (int np = 0; np < 4; np++) {
            uint32_t r4b[4];
            uint32_t r = (uint32_t)((np * 16 + arow) * QK_ROWB + (kk * 16 + acsel) * 2);
            LDMATRIX_X4(r4b, sb + 2*QK_MAT + r);
            bf[np*2][0] = r4b[0]; bf[np*2][1] = r4b[2];
            bf[np*2+1][0] = r4b[1]; bf[np*2+1][1] = r4b[3];
        }
#pragma unroll
        for (int nt = 0; nt < 8; nt++) MMA_BF16(qa[nt], Ah[kk], bf[nt]);
        // K
#pragma unroll
        for (int np = 0; np < 4; np++) {
            uint32_t r4b[4];
            uint32_t r = (uint32_t)((np * 16 + arow) * QK_ROWB + (kk * 16 + acsel) * 2);
            LDMATRIX_X4(r4b, sb + 3*QK_MAT + r);
            bf[np*2][0] = r4b[0]; bf[np*2][1] = r4b[2];
            bf[np*2+1][0] = r4b[1]; bf[np*2+1][1] = r4b[3];
        }
#pragma unroll
        for (int nt = 0; nt < 8; nt++) MMA_BF16(ka[nt], Ah[kk], bf[nt]);
        // V (split, 3 products, product-major)
        uint32_t bvl[8][2];
#pragma unroll
        for (int np = 0; np < 4; np++) {
            uint32_t r4b[4];
            uint32_t r = (uint32_t)((np * 16 + arow) * QK_ROWB + (kk * 16 + acsel) * 2);
            LDMATRIX_X4(r4b, sb + 4*QK_MAT + r);
            bf[np*2][0] = r4b[0]; bf[np*2][1] = r4b[2];
            bf[np*2+1][0] = r4b[1]; bf[np*2+1][1] = r4b[3];
            LDMATRIX_X4(r4b, sb + 5*QK_MAT + r);
            bvl[np*2][0] = r4b[0]; bvl[np*2][1] = r4b[2];
            bvl[np*2+1][0] = r4b[1]; bvl[np*2+1][1] = r4b[3];
        }
#pragma unroll
        for (int nt = 0; nt < 8; nt++) MMA_BF16(va[nt], Ah[kk], bf[nt]);
#pragma unroll
        for (int nt = 0; nt < 8; nt++) MMA_BF16(va[nt], Ah[kk], bvl[nt]);
#pragma unroll
        for (int nt = 0; nt < 8; nt++) MMA_BF16(va[nt], Al[kk], bf[nt]);
    }

    // ---- epilogue ----
    const int r4 = lane >> 2;
    const int c2 = (lane & 3) * 2;
    const int s_lo = qt * 64 + w * 16 + r4;
    const int s_hi = s_lo + 8;
#pragma unroll
    for (int nt = 0; nt < 8; nt++) {
        int e = nt * 8 + c2;
        size_t ilo = ((size_t)bh * SP + s_lo) * HD + e;
        size_t ihi = ((size_t)bh * SP + s_hi) * HD + e;
        *(uint32_t*)(qh + ilo) = pk2(qa[nt][0] * 0.125f, qa[nt][1] * 0.125f);
        *(uint32_t*)(qh + ihi) = pk2(qa[nt][2] * 0.125f, qa[nt][3] * 0.125f);
        *(uint32_t*)(kh + ilo) = pk2(ka[nt][0], ka[nt][1]);
        *(uint32_t*)(kh + ihi) = pk2(ka[nt][2], ka[nt][3]);
        float v0 = va[nt][0], v1 = va[nt][1], v2 = va[nt][2], v3 = va[nt][3];
        float h0 = __bfloat162float(__float2bfloat16(v0));
        float h1 = __bfloat162float(__float2bfloat16(v1));
        float h2 = __bfloat162float(__float2bfloat16(v2));
        float h3 = __bfloat162float(__float2bfloat16(v3));
        *(uint32_t*)(vh + ilo) = pk2(v0, v1);
        *(uint32_t*)(vh + ihi) = pk2(v2, v3);
        *(uint32_t*)(vl + ilo) = pk2(v0 - h0, v1 - h1);
        *(uint32_t*)(vl + ihi) = pk2(v2 - h2, v3 - h3);
    }
}

// ---------------------------------------------------------------------------
// Attention v3: FA2-style mma.sync flash attention (unchanged from R13).
// ---------------------------------------------------------------------------
#define AT_ROW   144
#define AT_MAT   9216
#define AT_STAGE 27648
#define AT_SMEM  (AT_MAT + 2*AT_STAGE)

__global__ __launch_bounds__(128) void attn3_kernel(
        const __nv_bfloat16* __restrict__ Qh,
        const __nv_bfloat16* __restrict__ Kh,
        const __nv_bfloat16* __restrict__ Vh,
        const __nv_bfloat16* __restrict__ Vl,
        __nv_bfloat16* __restrict__ Oh,
        __nv_bfloat16* __restrict__ Ol)
{
    extern __shared__ char asmem[];
    const uint32_t sb   = smem_u32(asmem);
    const int bh   = blockIdx.x;
    const int qt   = blockIdx.y;
    const int tid  = threadIdx.x;
    const int lane = tid & 31;
    const int w    = tid >> 5;

    const size_t gbase = (size_t)bh * SP * HD;

    const int srow = tid >> 3;
    const int sc8  = (tid & 7) * 8;

#pragma unroll
    for (int it = 0; it < 4; it++) {
        int r = srow + it * 16;
        cp16(sb + r * AT_ROW + sc8 * 2,
             Qh + gbase + (size_t)(qt * 64 + r) * HD + sc8);
    }
    {
        const uint32_t base = sb + AT_MAT;
#pragma unroll
        for (int it = 0; it < 4; it++) {
            int r = srow + it * 16;
            size_t gi = gbase + (size_t)r * HD + sc8;
            uint32_t d = base + r * AT_ROW + sc8 * 2;
            cp16(d,              Kh + gi);
            cp16(d + AT_MAT,     Vh + gi);
            cp16(d + 2*AT_MAT,   Vl + gi);
        }
    }
    CP_COMMIT();

    const int l16   = lane & 15;
    const int arow  = l16;
    const int acsel = (lane >> 4) * 8;
    const int kbrow = l16 & 7;
    const int kbsel = (l16 >> 3) * 8;
    const int vrow  = l16;
    const int vcsel = (lane & 16) ? 8 : 0;

    uint32_t qf[4][4];
    float of[8][4] = {};
    float m_lo = -1e30f, m_hi = -1e30f, l_lo = 0.f, l_hi = 0.f;

    CP_WAIT0();
    __syncthreads();

#pragma unroll
    for (int kk = 0; kk < 4; kk++) {
        uint32_t a = sb + (w * 16 + arow) * AT_ROW + (kk * 16 + acsel) * 2;
        LDMATRIX_X4(qf[kk], a);
    }

    for (int kt = 0; kt < SP / 64; kt++) {
        if (kt > 0) { CP_WAIT0(); __syncthreads(); }
        if (kt + 1 < SP / 64) {
            const uint32_t base = sb + AT_MAT + ((kt + 1) & 1) * AT_STAGE;
            const size_t   gr   = gbase + (size_t)((kt + 1) * 64) * HD;
#pragma unroll
            for (int it = 0; it < 4; it++) {
                int r = srow + it * 16;
                size_t gi = gr + (size_t)r * HD + sc8;
                uint32_t d = base + r * AT_ROW + sc8 * 2;
                cp16(d,            Kh + gi);
                cp16(d + AT_MAT,   Vh + gi);
                cp16(d + 2*AT_MAT, Vl + gi);
            }
            CP_COMMIT();
        }
        const uint32_t kb = sb + AT_MAT + (kt & 1) * AT_STAGE;

        float sf[8][4];
#pragma unroll
        for (int nt = 0; nt < 8; nt++)
            sf[nt][0] = sf[nt][1] = sf[nt][2] = sf[nt][3] = 0.f;
#pragma unroll
        for (int kk = 0; kk < 4; kk++) {
#pragma unroll
            for (int nt = 0; nt < 8; nt++) {
                uint32_t bfr[2];
                LDMATRIX_X2(bfr, kb + (nt * 8 + kbrow) * AT_ROW + (kk * 16 + kbsel) * 2);
                MMA_BF16(sf[nt], qf[kk], bfr);
            }
        }
        if (kt == SP / 64 - 1) {
#pragma unroll
            for (int nt = 5; nt < 8; nt++)
                sf[nt][0] = sf[nt][1] = sf[nt][2] = sf[nt][3] = -1e30f;
        }

        float ml = -1e30f, mh = -1e30f;
#pragma unroll
        for (int nt = 0; nt < 8; nt++) {
            ml = fmaxf(ml, fmaxf(sf[nt][0], sf[nt][1]));
            mh = fmaxf(mh, fmaxf(sf[nt][2], sf[nt][3]));
        }
        ml = fmaxf(ml, __shfl_xor_sync(0xffffffffu, ml, 1));
        ml = fmaxf(ml, __shfl_xor_sync(0xffffffffu, ml, 2));
        mh = fmaxf(mh, __shfl_xor_sync(0xffffffffu, mh, 1));
        mh = fmaxf(mh, __shfl_xor_sync(0xffffffffu, mh, 2));

        float nml = fmaxf(m_lo, ml), nmh = fmaxf(m_hi, mh);
        float cl = __expf(m_lo - nml), ch = __expf(m_hi - nmh);
        m_lo = nml; m_hi = nmh;
        l_lo *= cl; l_hi *= ch;

#pragma unroll
        for (int nt = 0; nt < 8; nt++) {
            float p0 = __expf(sf[nt][0] - nml);
            float p1 = __expf(sf[nt][1] - nml);
            float p2 = __expf(sf[nt][2] - nmh);
            float p3 = __expf(sf[nt][3] - nmh);
            l_lo += p0 + p1;  l_hi += p2 + p3;
            sf[nt][0] = p0; sf[nt][1] = p1; sf[nt][2] = p2; sf[nt][3] = p3;
        }
#pragma unroll
        for (int dt = 0; dt < 8; dt++) {
            of[dt][0] *= cl; of[dt][1] *= cl;
            of[dt][2] *= ch; of[dt][3] *= ch;
        }

        const uint32_t vbh = kb + AT_MAT;
        const uint32_t vbl = kb + 2 * AT_MAT;
#pragma unroll
        for (int kc = 0; kc < 4; kc++) {
            const float* pA = sf[2 * kc];
            const float* pB = sf[2 * kc + 1];
            uint32_t ah[4], al[4];
            ah[0] = pk2(pA[0], pA[1]);
            ah[1] = pk2(pA[2], pA[3]);
            ah[2] = pk2(pB[0], pB[1]);
            ah[3] = pk2(pB[2], pB[3]);
            {
                float rA0 = pA[0] - __bfloat162float(__float2bfloat16(pA[0]));
                float rA1 = pA[1] - __bfloat162float(__float2bfloat16(pA[1]));
                float rA2 = pA[2] - __bfloat162float(__float2bfloat16(pA[2]));
                float rA3 = pA[3] - __bfloat162float(__float2bfloat16(pA[3]));
                float rB0 = pB[0] - __bfloat162float(__float2bfloat16(pB[0]));
                float rB1 = pB[1] - __bfloat162float(__float2bfloat16(pB[1]));
                float rB2 = pB[2] - __bfloat162float(__float2bfloat16(pB[2]));
                float rB3 = pB[3] - __bfloat162float(__float2bfloat16(pB[3]));
                al[0] = pk2(rA0, rA1);
                al[1] = pk2(rA2, rA3);
                al[2] = pk2(rB0, rB1);
                al[3] = pk2(rB2, rB3);
            }
#pragma unroll
            for (int dtp = 0; dtp < 4; dtp++) {
                uint32_t vh4[4], vl4[4];
                uint32_t vaddr = (kc * 16 + vrow) * AT_ROW + (dtp * 16 + vcsel) * 2;
                LDMATRIX_X4T(vh4, vbh + vaddr);
                LDMATRIX_X4T(vl4, vbl + vaddr);
                uint32_t bh0[2] = { vh4[0], vh4[1] };
                uint32_t bh1[2] = { vh4[2], vh4[3] };
                uint32_t bl0[2] = { vl4[0], vl4[1] };
                uint32_t bl1[2] = { vl4[2], vl4[3] };
                MMA_BF16(of[2 * dtp],     ah, bh0);
                MMA_BF16(of[2 * dtp + 1], ah, bh1);
                MMA_BF16(of[2 * dtp],     ah, bl0);
                MMA_BF16(of[2 * dtp + 1], ah, bl1);
                MMA_BF16(of[2 * dtp],     al, bh0);
                MMA_BF16(of[2 * dtp + 1], al, bh1);
            }
        }
    }

    l_lo += __shfl_xor_sync(0xffffffffu, l_lo, 1);
    l_lo += __shfl_xor_sync(0xffffffffu, l_lo, 2);
    l_hi += __shfl_xor_sync(0xffffffffu, l_hi, 1);
    l_hi += __shfl_xor_sync(0xffffffffu, l_hi, 2);
    float il = 1.f / l_lo, ih = 1.f / l_hi;

    const int b    = bh >> 3;
    const int hh2  = bh & 7;
    const int s_lo = qt * 64 + w * 16 + (lane >> 2);
    const int s_hi = s_lo + 8;
    const int dcol = hh2 * HD + 2 * (lane & 3);

#pragma unroll
    for (int dt = 0; dt < 8; dt++) {
        int d = dcol + dt * 8;
        if (s_lo < SS) {
            float v0 = of[dt][0] * il, v1 = of[dt][1] * il;
            float h0 = __bfloat162float(__float2bfloat16(v0));
            float h1 = __bfloat162float(__float2bfloat16(v1));
            size_t idx = (size_t)(b * SS + s_lo) * DD + d;
            *(uint32_t*)(Oh + idx) = pk2(v0, v1);
            *(uint32_t*)(Ol + idx) = pk2(v0 - h0, v1 - h1);
        }
        if (s_hi < SS) {
            float v2 = of[dt][2] * ih, v3 = of[dt][3] * ih;
            float h2 = __bfloat162float(__float2bfloat16(v2));
            float h3 = __bfloat162float(__float2bfloat16(v3));
            size_t idx = (size_t)(b * SS + s_hi) * DD + d;
            *(uint32_t*)(Oh + idx) = pk2(v2, v3);
            *(uint32_t*)(Ol + idx) = pk2(v2 - h2, v3 - h3);
        }
    }
}

// ---------------------------------------------------------------------------
// Tensor-core GEMM (unchanged from R13: product-major, x4 B-ldmatrix).
// ---------------------------------------------------------------------------
#define G_ROWB   80
#define G_MAT    10240
#define G_STAGE  40960
#define G_SMEM   81920

template<bool RELU, bool RESID, bool RSPLIT, bool PACKOUT>
__global__ __launch_bounds__(256, 2) void gemm_mma_kernel(
        const __nv_bfloat16* __restrict__ Ah, const __nv_bfloat16* __restrict__ Al,
        const __nv_bfloat16* __restrict__ Wh, const __nv_bfloat16* __restrict__ Wl,
        const float* __restrict__ bias,
        const float* __restrict__ R,
        const __nv_bfloat16* __restrict__ Rh, const __nv_bfloat16* __restrict__ Rl,
        float* __restrict__ Cf,
        __nv_bfloat16* __restrict__ Ch, __nv_bfloat16* __restrict__ Cl,
        int M, int N, int K)
{
    extern __shared__ char dsm[];
    const uint32_t sb = smem_u32(dsm);

    const int tid  = threadIdx.x;
    const int lane = tid & 31;
    const int wid  = tid >> 5;
    const int wm   = (wid & 1) * 64;
    const int wn   = (wid >> 1) * 32;
    const int m0   = blockIdx.y * 128;
    const int n0   = blockIdx.x * 128;

    float acc[4][4][4] = {};

    const int prow0 = tid >> 2;
    const int prow1 = prow0 + 64;
    const int pc8   = (tid & 3) * 8;
    const uint32_t pdst0 = (uint32_t)(prow0 * G_ROWB + pc8 * 2);
    const uint32_t pdst1 = (uint32_t)(prow1 * G_ROWB + pc8 * 2);

    const int arow  = lane & 15;
    const int acsel = (lane >> 4) * 8;

    const int nchunk = K >> 5;

    auto prefetch = [&](int kc, int st) {
        const int k0 = kc << 5;
        const uint32_t s0 = sb + st * G_STAGE;
        cp16(s0 + 0*G_MAT + pdst0, Ah + (size_t)(m0 + prow0) * K + k0 + pc8);
        cp16(s0 + 0*G_MAT + pdst1, Ah + (size_t)(m0 + prow1) * K + k0 + pc8);
        cp16(s0 + 1*G_MAT + pdst0, Al + (size_t)(m0 + prow0) * K + k0 + pc8);
        cp16(s0 + 1*G_MAT + pdst1, Al + (size_t)(m0 + prow1) * K + k0 + pc8);
        cp16(s0 + 2*G_MAT + pdst0, Wh + (size_t)(n0 + prow0) * K + k0 + pc8);
        cp16(s0 + 2*G_MAT + pdst1, Wh + (size_t)(n0 + prow1) * K + k0 + pc8);
        cp16(s0 + 3*G_MAT + pdst0, Wl + (size_t)(n0 + prow0) * K + k0 + pc8);
        cp16(s0 + 3*G_MAT + pdst1, Wl + (size_t)(n0 + prow1) * K + k0 + pc8);
    };

    prefetch(0, 0);
    CP_COMMIT();

    for (int kc = 0; kc < nchunk; kc++) {
        const int st = kc & 1;
        if (kc + 1 < nchunk) {
            prefetch(kc + 1, st ^ 1);
            CP_COMMIT();
            CP_WAIT1();
        } else {
            CP_WAIT0();
        }
        __syncthreads();

        const uint32_t s0 = sb + st * G_STAGE;
#pragma unroll
        for (int ks = 0; ks < 2; ks++) {
            const int kcol = ks * 16;

            uint32_t bh[4][2], bl[4][2];
#pragma unroll
            for (int np = 0; np < 2; np++) {
                uint32_t r4b[4];
                uint32_t r = (uint32_t)((wn + np * 16 + arow) * G_ROWB + (kcol + acsel) * 2);
                LDMATRIX_X4(r4b, s0 + 2*G_MAT + r);
                bh[np*2    ][0] = r4b[0]; bh[np*2    ][1] = r4b[2];
                bh[np*2 + 1][0] = r4b[1]; bh[np*2 + 1][1] = r4b[3];
                LDMATRIX_X4(r4b, s0 + 3*G_MAT + r);
                bl[np*2    ][0] = r4b[0]; bl[np*2    ][1] = r4b[2];
                bl[np*2 + 1][0] = r4b[1]; bl[np*2 + 1][1] = r4b[3];
            }
#pragma unroll
            for (int mt = 0; mt < 4; mt++) {
                uint32_t ahf[4], alf[4];
                uint32_t r = (uint32_t)((wm + mt * 16 + arow) * G_ROWB + (kcol + acsel) * 2);
                LDMATRIX_X4(ahf, s0 + 0*G_MAT + r);
                LDMATRIX_X4(alf, s0 + 1*G_MAT + r);
#pragma unroll
                for (int nt = 0; nt < 4; nt++) MMA_BF16(acc[mt][nt], ahf, bh[nt]);
#pragma unroll
                for (int nt = 0; nt < 4; nt++) MMA_BF16(acc[mt][nt], ahf, bl[nt]);
#pragma unroll
                for (int nt = 0; nt < 4; nt++) MMA_BF16(acc[mt][nt], alf, bh[nt]);
            }
        }
        __syncthreads();
    }

    const int r4 = lane >> 2;
    const int c2 = (lane & 3) * 2;
#pragma unroll
    for (int mt = 0; mt < 4; mt++) {
#pragma unroll
        for (int nt = 0; nt < 4; nt++) {
#pragma unroll
            for (int e = 0; e < 4; e++) {
                int mg = m0 + wm + mt * 16 + r4 + (e >> 1) * 8;
                int ng = n0 + wn + nt * 8 + c2 + (e & 1);
                float v = acc[mt][nt][e] + bias[ng];
                if (RELU)  v = fmaxf(v, 0.f);
                if (RESID) {
                    if (RSPLIT)
                        v += __bfloat162float(Rh[(size_t)mg * N + ng])
                           + __bfloat162float(Rl[(size_t)mg * N + ng]);
                    else
                        v += R[(size_t)mg * N + ng];
                }
                if (PACKOUT) {
                    __nv_bfloat16 hb = __float2bfloat16(v);
                    Ch[(size_t)mg * N + ng] = hb;
                    Cl[(size_t)mg * N + ng] = __float2bfloat16(v - __bfloat162float(hb));
                } else {
                    Cf[(size_t)mg * N + ng] = v;
                }
            }
        }
    }
}

// ---------------------------------------------------------------------------
// LayerNorm; PACK=1 writes only the split-bf16 pair, PACK=0 only fp32.
// ---------------------------------------------------------------------------
template<bool PACK>
__global__ void ln_kernel(const float* __restrict__ x,
                          const float* __restrict__ w,
                          const float* __restrict__ b,
                          float* __restrict__ y,
                          __nv_bfloat16* __restrict__ yh,
                          __nv_bfloat16* __restrict__ yl)
{
    int r = blockIdx.x;
    int t = threadIdx.x;
    const float* xr = x + (size_t)r * DD;

    float v0 = xr[t], v1 = xr[t + 256];
    float s  = v0 + v1;
    float sq = v0 * v0 + v1 * v1;

#pragma unroll
    for (int off = 16; off; off >>= 1) {
        s  += __shfl_xor_sync(0xffffffffu, s,  off);
        sq += __shfl_xor_sync(0xffffffffu, sq, off);
    }
    __shared__ float sw[8], sqw[8];
    if ((t & 31) == 0) { sw[t >> 5] = s; sqw[t >> 5] = sq; }
    __syncthreads();
    s  = sw[0] + sw[1] + sw[2] + sw[3] + sw[4] + sw[5] + sw[6] + sw[7];
    sq = sqw[0] + sqw[1] + sqw[2] + sqw[3] + sqw[4] + sqw[5] + sqw[6] + sqw[7];

    float mean = s * (1.f / DD);
    float var  = sq * (1.f / DD) - mean * mean;
    float inv  = rsqrtf(var + 1e-5f);

    float r0 = (v0 - mean) * inv * w[t]       + b[t];
    float r1 = (v1 - mean) * inv * w[t + 256] + b[t + 256];
    if (!PACK) {
        float* yr = y + (size_t)r * DD;
        yr[t]       = r0;
        yr[t + 256] = r1;
    } else {
        size_t base = (size_t)r * DD;
        __nv_bfloat16 h0 = __float2bfloat16(r0);
        __nv_bfloat16 h1 = __float2bfloat16(r1);
        yh[base + t]       = h0;
        yh[base + t + 256] = h1;
        yl[base + t]       = __float2bfloat16(r0 - __bfloat162float(h0));
        yl[base + t + 256] = __float2bfloat16(r1 - __bfloat162float(h1));
    }
}

// ---------------------------------------------------------------------------
// Host launcher
// ---------------------------------------------------------------------------
extern "C" void kernel_launch(void* const* d_in, const int* in_sizes, int n_in,
                              void* d_out, int out_size)
{
    const int*   x    = (const int*)  d_in[0];
    const float* emb  = (const float*)d_in[1];
    const float* pe   = (const float*)d_in[2];
    const float* Wq   = (const float*)d_in[3];
    const float* Wk   = (const float*)d_in[4];
    const float* Wv   = (const float*)d_in[5];
    const float* Wo   = (const float*)d_in[6];
    const float* bo   = (const float*)d_in[7];
    const float* ln1w = (const float*)d_in[8];
    const float* ln1b = (const float*)d_in[9];
    const float* W1   = (const float*)d_in[10];
    const float* b1   = (const float*)d_in[11];
    const float* W2   = (const float*)d_in[12];
    const float* b2   = (const float*)d_in[13];
    const float* ln2w = (const float*)d_in[14];
    const float* ln2b = (const float*)d_in[15];
    float* out = (float*)d_out;

    float *t;
    __nv_bfloat16 *hhp, *hlp, *qh, *kh, *vh, *vl;
    __nv_bfloat16 *oh, *ol, *n1h, *n1l, *ffh, *ffl;
    __nv_bfloat16 *woh, *wol, *w1h, *w1l, *w2h, *w2l;
    cudaGetSymbolAddress((void**)&t,   g_t);
    cudaGetSymbolAddress((void**)&hhp, g_hh);
    cudaGetSymbolAddress((void**)&hlp, g_hl);
    cudaGetSymbolAddress((void**)&qh,  g_qh);
    cudaGetSymbolAddress((void**)&kh,  g_kh);
    cudaGetSymbolAddress((void**)&vh,  g_vh);
    cudaGetSymbolAddress((void**)&vl,  g_vl);
    cudaGetSymbolAddress((void**)&oh,  g_oh);
    cudaGetSymbolAddress((void**)&ol,  g_ol);
    cudaGetSymbolAddress((void**)&n1h, g_n1h);
    cudaGetSymbolAddress((void**)&n1l, g_n1l);
    cudaGetSymbolAddress((void**)&ffh, g_ffh);
    cudaGetSymbolAddress((void**)&ffl, g_ffl);
    cudaGetSymbolAddress((void**)&woh, g_woh);
    cudaGetSymbolAddress((void**)&wol, g_wol);
    cudaGetSymbolAddress((void**)&w1h, g_w1h);
    cudaGetSymbolAddress((void**)&w1l, g_w1l);
    cudaGetSymbolAddress((void**)&w2h, g_w2h);
    cudaGetSymbolAddress((void**)&w2l, g_w2l);

    cudaFuncSetAttribute(gemm_mma_kernel<false, true,  true,  false>,
                         cudaFuncAttributeMaxDynamicSharedMemorySize, G_SMEM);
    cudaFuncSetAttribute(gemm_mma_kernel<true,  false, false, true>,
                         cudaFuncAttributeMaxDynamicSharedMemorySize, G_SMEM);
    cudaFuncSetAttribute(attn3_kernel,
                         cudaFuncAttributeMaxDynamicSharedMemorySize, AT_SMEM);
    cudaFuncSetAttribute(qkv3_kernel<true>,
                         cudaFuncAttributeMaxDynamicSharedMemorySize, QK_SMEM);
    cudaFuncSetAttribute(qkv3_kernel<false>,
                         cudaFuncAttributeMaxDynamicSharedMemorySize, QK_SMEM);

    // Launch order puts gemm_mma (Wo, layer 0) at index 3 for the profiler.
    pack_all_kernel<<<(PTOT + 255) / 256, 256>>>(Wo, W1, W2,               // 0
                                                 woh, wol, w1h, w1l, w2h, w2l);

    for (int l = 0; l < LL; l++) {
        if (l == 0)
            qkv3_kernel<true><<<dim3(BB * HH, SP / 64), 128, QK_SMEM>>>(    // 1
                nullptr, nullptr, x, emb, pe,
                Wq, Wk, Wv, qh, kh, vh, vl, hhp, hlp);
        else
            qkv3_kernel<false><<<dim3(BB * HH, SP / 64), 128, QK_SMEM>>>(
                hhp, hlp, nullptr, nullptr, nullptr,
                Wq + l * HD * HD, Wk + l * HD * HD, Wv + l * HD * HD,
                qh, kh, vh, vl, nullptr, nullptr);

        attn3_kernel<<<dim3(BB * HH, SP / 64), 128, AT_SMEM>>>(             // 2
            qh, kh, vh, vl, oh, ol);

        // t = o @ Wo^T + bo + h   (split residual, fp32 out)                  3 <- profiled
        gemm_mma_kernel<false, true, true, false><<<dim3(DD / 128, MM / 128), 256, G_SMEM>>>(
            oh, ol, woh + (size_t)l * DD * DD, wol + (size_t)l * DD * DD,
            bo + l * DD, nullptr, hhp, hlp, t, nullptr, nullptr, MM, DD, DD);

        ln_kernel<true><<<MM, 256>>>(t, ln1w + l * DD, ln1b + l * DD,
                                     nullptr, n1h, n1l);

        // ff = relu(n1 @ W1^T + b1)  (split-bf16 out)
        gemm_mma_kernel<true, false, false, true><<<dim3(FF / 128, MM / 128), 256, G_SMEM>>>(
            n1h, n1l, w1h + (size_t)l * FF * DD, w1l + (size_t)l * FF * DD,
            b1 + l * FF, nullptr, nullptr, nullptr, nullptr, ffh, ffl, MM, FF, DD);

        // t = ff @ W2^T + b2 + n1  (split residual, fp32 out)
        gemm_mma_kernel<false, true, true, false><<<dim3(DD / 128, MM / 128), 256, G_SMEM>>>(
            ffh, ffl, w2h + (size_t)l * DD * FF, w2l + (size_t)l * DD * FF,
            b2 + l * DD, nullptr, n1h, n1l, t, nullptr, nullptr, MM, DD, FF);

        if (l == LL - 1)
            ln_kernel<false><<<MM, 256>>>(t, ln2w + l * DD, ln2b + l * DD,
                                          out, nullptr, nullptr);
        else
            ln_kernel<true><<<MM, 256>>>(t, ln2w + l * DD, ln2b + l * DD,
                                         nullptr, hhp, hlp);
    }
}

// round 17
// speedup vs baseline: 1.4616x; 1.4616x over previous
#include <cuda_runtime.h>
#include <cuda_bf16.h>
#include <math.h>
#include <stdint.h>

// Problem constants
#define BB 32
#define SS 744
#define SP 768          // padded sequence for mma attention
#define DD 512
#define HH 8
#define HD 64
#define LL 4
#define MM (BB*SS)      // 23808 = 128*186
#define FF (4*DD)       // 2048

__device__ __forceinline__ uint32_t smem_u32(const void* p) {
    uint32_t a;
    asm("{ .reg .u64 t; cvta.to.shared.u64 t, %1; cvt.u32.u64 %0, t; }" : "=r"(a) : "l"(p));
    return a;
}
__device__ __forceinline__ void cp16(uint32_t dst, const void* src) {
    asm volatile("cp.async.cg.shared.global [%0], [%1], 16;" :: "r"(dst), "l"(src) : "memory");
}
#define CP_COMMIT() asm volatile("cp.async.commit_group;" ::: "memory")
#define CP_WAIT1()  asm volatile("cp.async.wait_group 1;" ::: "memory")
#define CP_WAIT0()  asm volatile("cp.async.wait_group 0;" ::: "memory")

// pack two f32 -> bf16x2 (first arg in bits 0-15)
__device__ __forceinline__ uint32_t pk2(float lo, float hi) {
    uint32_t r;
    asm("cvt.rn.bf16x2.f32 %0, %1, %2;" : "=r"(r) : "f"(hi), "f"(lo));
    return r;
}

#define MMA_BF16(c, a, b) \
    asm volatile("mma.sync.aligned.m16n8k16.row.col.f32.bf16.bf16.f32 " \
        "{%0,%1,%2,%3}, {%4,%5,%6,%7}, {%8,%9}, {%0,%1,%2,%3};" \
        : "+f"((c)[0]), "+f"((c)[1]), "+f"((c)[2]), "+f"((c)[3]) \
        : "r"((a)[0]), "r"((a)[1]), "r"((a)[2]), "r"((a)[3]), \
          "r"((b)[0]), "r"((b)[1]))

#define LDMATRIX_X4(r, addr) \
    asm volatile("ldmatrix.sync.aligned.m8n8.x4.shared.b16 {%0,%1,%2,%3}, [%4];" \
        : "=r"((r)[0]), "=r"((r)[1]), "=r"((r)[2]), "=r"((r)[3]) : "r"(addr))

#define LDMATRIX_X4T(r, addr) \
    asm volatile("ldmatrix.sync.aligned.m8n8.x4.trans.shared.b16 {%0,%1,%2,%3}, [%4];" \
        : "=r"((r)[0]), "=r"((r)[1]), "=r"((r)[2]), "=r"((r)[3]) : "r"(addr))

#define LDMATRIX_X2(r, addr) \
    asm volatile("ldmatrix.sync.aligned.m8n8.x2.shared.b16 {%0,%1}, [%2];" \
        : "=r"((r)[0]), "=r"((r)[1]) : "r"(addr))

// ---------------------------------------------------------------------------
// Scratch (device globals)
// ---------------------------------------------------------------------------
__device__ float g_h [MM*DD];
__device__ float g_t [MM*DD];
// bf16 attention operands, padded to SP rows, layout [B*H, SP, HD]
__device__ __nv_bfloat16 g_qh[(size_t)BB*HH*SP*HD];   // pre-scaled by 0.125
__device__ __nv_bfloat16 g_kh[(size_t)BB*HH*SP*HD];
__device__ __nv_bfloat16 g_vh[(size_t)BB*HH*SP*HD];
__device__ __nv_bfloat16 g_vl[(size_t)BB*HH*SP*HD];
// split-bf16 activations (hi, lo)
__device__ __nv_bfloat16 g_oh [MM*DD];
__device__ __nv_bfloat16 g_ol [MM*DD];
__device__ __nv_bfloat16 g_n1h[MM*DD];
__device__ __nv_bfloat16 g_n1l[MM*DD];
__device__ __nv_bfloat16 g_ffh[(size_t)MM*FF];
__device__ __nv_bfloat16 g_ffl[(size_t)MM*FF];
// split-bf16 weights
__device__ __nv_bfloat16 g_woh[LL*DD*DD];
__device__ __nv_bfloat16 g_wol[LL*DD*DD];
__device__ __nv_bfloat16 g_w1h[LL*FF*DD];
__device__ __nv_bfloat16 g_w1l[LL*FF*DD];
__device__ __nv_bfloat16 g_w2h[(size_t)LL*DD*FF];
__device__ __nv_bfloat16 g_w2l[(size_t)LL*DD*FF];

// ---------------------------------------------------------------------------
// Pack all big weights fp32 -> split-bf16 in ONE launch
// ---------------------------------------------------------------------------
#define PN1 (LL*DD*DD)    // 1048576
#define PN2 (LL*FF*DD)    // 4194304
#define PTOT (PN1 + 2*PN2)

__global__ void pack_all_kernel(const float* __restrict__ Wo,
                                const float* __restrict__ W1,
                                const float* __restrict__ W2,
                                __nv_bfloat16* __restrict__ woh, __nv_bfloat16* __restrict__ wol,
                                __nv_bfloat16* __restrict__ w1h, __nv_bfloat16* __restrict__ w1l,
                                __nv_bfloat16* __restrict__ w2h, __nv_bfloat16* __restrict__ w2l)
{
    int i = blockIdx.x * 256 + threadIdx.x;
    const float* src; __nv_bfloat16 *dh, *dl; int j;
    if (i < PN1)            { src = Wo; dh = woh; dl = wol; j = i; }
    else if (i < PN1 + PN2) { src = W1; dh = w1h; dl = w1l; j = i - PN1; }
    else if (i < PTOT)      { src = W2; dh = w2h; dl = w2l; j = i - PN1 - PN2; }
    else return;
    float v = src[j];
    __nv_bfloat16 hb = __float2bfloat16(v);
    dh[j] = hb;
    dl[j] = __float2bfloat16(v - __bfloat162float(hb));
}

// ---------------------------------------------------------------------------
// Embedding
// ---------------------------------------------------------------------------
__global__ void embed_kernel(const int* __restrict__ x,
                             const float* __restrict__ emb,
                             const float* __restrict__ pe,
                             float* __restrict__ h)
{
    int idx = blockIdx.x * 256 + threadIdx.x;
    int d   = idx & (DD - 1);
    int ms  = idx >> 9;
    int s   = ms % SS;
    int tok = x[ms];
    h[idx] = emb[tok * DD + d] * 22.627416997969522f + pe[s * DD + d];
}

// ---------------------------------------------------------------------------
// QKV: smem micro-GEMM (fp32 math), bf16 outputs, padded to SP rows.
// grid = (B*H, SP/32, 2); block = 256.
// ---------------------------------------------------------------------------
__global__ __launch_bounds__(256) void qkv2_kernel(
        const float* __restrict__ h,
        const float* __restrict__ Wq,
        const float* __restrict__ Wk,
        const float* __restrict__ Wv,
        __nv_bfloat16* __restrict__ qh,
        __nv_bfloat16* __restrict__ kh,
        __nv_bfloat16* __restrict__ vh,
        __nv_bfloat16* __restrict__ vl)
{
    __shared__ float Ws3[3][HD][33];
    __shared__ float Xs[32][HD];

    const int bh  = blockIdx.x;
    const int b   = bh >> 3;
    const int hh  = bh & 7;
    const int s0  = blockIdx.y * 32;
    const int e0  = blockIdx.z * 32;
    const int tid = threadIdx.x;

#pragma unroll
    for (int i = 0; i < 6; i++) {
        int idx = tid + i * 256;
        int m   = idx >> 9;
        int r   = idx & 511;
        int el  = r >> 4;
        int d4  = (r & 15) * 4;
        const float* Wm = (m == 0) ? Wq : (m == 1) ? Wk : Wv;
        float4 a = *(const float4*)(Wm + (e0 + el) * HD + d4);
        Ws3[m][d4 + 0][el] = a.x;
        Ws3[m][d4 + 1][el] = a.y;
        Ws3[m][d4 + 2][el] = a.z;
        Ws3[m][d4 + 3][el] = a.w;
    }
#pragma unroll
    for (int i = 0; i < 2; i++) {
        int f   = tid + i * 256;
        int row = f >> 4;
        int c4  = f & 15;
        int sg  = s0 + row; if (sg > SS - 1) sg = SS - 1;
        ((float4*)Xs[row])[c4] =
            *(const float4*)(h + (size_t)(b * SS + sg) * DD + hh * HD + c4 * 4);
    }
    __syncthreads();

    const int el = tid & 31;
    const int ty = tid >> 5;

    float aq[4] = {}, ak[4] = {}, av[4] = {};
#pragma unroll
    for (int d = 0; d < HD; d++) {
        float wq = Ws3[0][d][el];
        float wk = Ws3[1][d][el];
        float wv = Ws3[2][d][el];
#pragma unroll
        for (int r = 0; r < 4; r++) {
            float xv = Xs[ty * 4 + r][d];
            aq[r] += xv * wq;
            ak[r] += xv * wk;
            av[r] += xv * wv;
        }
    }
#pragma unroll
    for (int r = 0; r < 4; r++) {
        int s = s0 + ty * 4 + r;
        size_t oi = ((size_t)bh * SP + s) * HD + e0 + el;
        if (s < SS) {
            qh[oi] = __float2bfloat16(aq[r] * 0.125f);
            kh[oi] = __float2bfloat16(ak[r]);
            __nv_bfloat16 hb = __float2bfloat16(av[r]);
            vh[oi] = hb;
            vl[oi] = __float2bfloat16(av[r] - __bfloat162float(hb));
        } else {
            qh[oi] = __float2bfloat16(0.f);
            kh[oi] = __float2bfloat16(0.f);
            vh[oi] = __float2bfloat16(0.f);
            vl[oi] = __float2bfloat16(0.f);
        }
    }
}

// ---------------------------------------------------------------------------
// Attention v3: FA2-style mma.sync flash attention.
// ---------------------------------------------------------------------------
#define AT_ROW   144
#define AT_MAT   9216
#define AT_STAGE 27648
#define AT_SMEM  (AT_MAT + 2*AT_STAGE)

__global__ __launch_bounds__(128) void attn3_kernel(
        const __nv_bfloat16* __restrict__ Qh,
        const __nv_bfloat16* __restrict__ Kh,
        const __nv_bfloat16* __restrict__ Vh,
        const __nv_bfloat16* __restrict__ Vl,
        __nv_bfloat16* __restrict__ Oh,
        __nv_bfloat16* __restrict__ Ol)
{
    extern __shared__ char asmem[];
    const uint32_t sb   = smem_u32(asmem);
    const int bh   = blockIdx.x;
    const int qt   = blockIdx.y;
    const int tid  = threadIdx.x;
    const int lane = tid & 31;
    const int w    = tid >> 5;

    const size_t gbase = (size_t)bh * SP * HD;

    const int srow = tid >> 3;
    const int sc8  = (tid & 7) * 8;

#pragma unroll
    for (int it = 0; it < 4; it++) {
        int r = srow + it * 16;
        cp16(sb + r * AT_ROW + sc8 * 2,
             Qh + gbase + (size_t)(qt * 64 + r) * HD + sc8);
    }
    {
        const uint32_t base = sb + AT_MAT;
#pragma unroll
        for (int it = 0; it < 4; it++) {
            int r = srow + it * 16;
            size_t gi = gbase + (size_t)r * HD + sc8;
            uint32_t d = base + r * AT_ROW + sc8 * 2;
            cp16(d,              Kh + gi);
            cp16(d + AT_MAT,     Vh + gi);
            cp16(d + 2*AT_MAT,   Vl + gi);
        }
    }
    CP_COMMIT();

    const int l16   = lane & 15;
    const int arow  = l16;
    const int acsel = (lane >> 4) * 8;
    const int kbrow = l16 & 7;
    const int kbsel = (l16 >> 3) * 8;
    const int vrow  = l16;
    const int vcsel = (lane & 16) ? 8 : 0;

    uint32_t qf[4][4];
    float of[8][4] = {};
    float m_lo = -1e30f, m_hi = -1e30f, l_lo = 0.f, l_hi = 0.f;

    CP_WAIT0();
    __syncthreads();

#pragma unroll
    for (int kk = 0; kk < 4; kk++) {
        uint32_t a = sb + (w * 16 + arow) * AT_ROW + (kk * 16 + acsel) * 2;
        LDMATRIX_X4(qf[kk], a);
    }

    for (int kt = 0; kt < SP / 64; kt++) {
        if (kt > 0) { CP_WAIT0(); __syncthreads(); }
        if (kt + 1 < SP / 64) {
            const uint32_t base = sb + AT_MAT + ((kt + 1) & 1) * AT_STAGE;
            const size_t   gr   = gbase + (size_t)((kt + 1) * 64) * HD;
#pragma unroll
            for (int it = 0; it < 4; it++) {
                int r = srow + it * 16;
                size_t gi = gr + (size_t)r * HD + sc8;
                uint32_t d = base + r * AT_ROW + sc8 * 2;
                cp16(d,            Kh + gi);
                cp16(d + AT_MAT,   Vh + gi);
                cp16(d + 2*AT_MAT, Vl + gi);
            }
            CP_COMMIT();
        }
        const uint32_t kb = sb + AT_MAT + (kt & 1) * AT_STAGE;

        float sf[8][4];
#pragma unroll
        for (int nt = 0; nt < 8; nt++)
            sf[nt][0] = sf[nt][1] = sf[nt][2] = sf[nt][3] = 0.f;
#pragma unroll
        for (int kk = 0; kk < 4; kk++) {
#pragma unroll
            for (int nt = 0; nt < 8; nt++) {
                uint32_t bfr[2];
                LDMATRIX_X2(bfr, kb + (nt * 8 + kbrow) * AT_ROW + (kk * 16 + kbsel) * 2);
                MMA_BF16(sf[nt], qf[kk], bfr);
            }
        }
        if (kt == SP / 64 - 1) {
#pragma unroll
            for (int nt = 5; nt < 8; nt++)
                sf[nt][0] = sf[nt][1] = sf[nt][2] = sf[nt][3] = -1e30f;
        }

        float ml = -1e30f, mh = -1e30f;
#pragma unroll
        for (int nt = 0; nt < 8; nt++) {
            ml = fmaxf(ml, fmaxf(sf[nt][0], sf[nt][1]));
            mh = fmaxf(mh, fmaxf(sf[nt][2], sf[nt][3]));
        }
        ml = fmaxf(ml, __shfl_xor_sync(0xffffffffu, ml, 1));
        ml = fmaxf(ml, __shfl_xor_sync(0xffffffffu, ml, 2));
        mh = fmaxf(mh, __shfl_xor_sync(0xffffffffu, mh, 1));
        mh = fmaxf(mh, __shfl_xor_sync(0xffffffffu, mh, 2));

        float nml = fmaxf(m_lo, ml), nmh = fmaxf(m_hi, mh);
        float cl = __expf(m_lo - nml), ch = __expf(m_hi - nmh);
        m_lo = nml; m_hi = nmh;
        l_lo *= cl; l_hi *= ch;

#pragma unroll
        for (int nt = 0; nt < 8; nt++) {
            float p0 = __expf(sf[nt][0] - nml);
            float p1 = __expf(sf[nt][1] - nml);
            float p2 = __expf(sf[nt][2] - nmh);
            float p3 = __expf(sf[nt][3] - nmh);
            l_lo += p0 + p1;  l_hi += p2 + p3;
            sf[nt][0] = p0; sf[nt][1] = p1; sf[nt][2] = p2; sf[nt][3] = p3;
        }
#pragma unroll
        for (int dt = 0; dt < 8; dt++) {
            of[dt][0] *= cl; of[dt][1] *= cl;
            of[dt][2] *= ch; of[dt][3] *= ch;
        }

        const uint32_t vbh = kb + AT_MAT;
        const uint32_t vbl = kb + 2 * AT_MAT;
#pragma unroll
        for (int kc = 0; kc < 4; kc++) {
            const float* pA = sf[2 * kc];
            const float* pB = sf[2 * kc + 1];
            uint32_t ah[4], al[4];
            ah[0] = pk2(pA[0], pA[1]);
            ah[1] = pk2(pA[2], pA[3]);
            ah[2] = pk2(pB[0], pB[1]);
            ah[3] = pk2(pB[2], pB[3]);
            {
                float rA0 = pA[0] - __bfloat162float(__float2bfloat16(pA[0]));
                float rA1 = pA[1] - __bfloat162float(__float2bfloat16(pA[1]));
                float rA2 = pA[2] - __bfloat162float(__float2bfloat16(pA[2]));
                float rA3 = pA[3] - __bfloat162float(__float2bfloat16(pA[3]));
                float rB0 = pB[0] - __bfloat162float(__float2bfloat16(pB[0]));
                float rB1 = pB[1] - __bfloat162float(__float2bfloat16(pB[1]));
                float rB2 = pB[2] - __bfloat162float(__float2bfloat16(pB[2]));
                float rB3 = pB[3] - __bfloat162float(__float2bfloat16(pB[3]));
                al[0] = pk2(rA0, rA1);
                al[1] = pk2(rA2, rA3);
                al[2] = pk2(rB0, rB1);
                al[3] = pk2(rB2, rB3);
            }
#pragma unroll
            for (int dtp = 0; dtp < 4; dtp++) {
                uint32_t vh4[4], vl4[4];
                uint32_t vaddr = (kc * 16 + vrow) * AT_ROW + (dtp * 16 + vcsel) * 2;
                LDMATRIX_X4T(vh4, vbh + vaddr);
                LDMATRIX_X4T(vl4, vbl + vaddr);
                uint32_t bh0[2] = { vh4[0], vh4[1] };
                uint32_t bh1[2] = { vh4[2], vh4[3] };
                uint32_t bl0[2] = { vl4[0], vl4[1] };
                uint32_t bl1[2] = { vl4[2], vl4[3] };
                MMA_BF16(of[2 * dtp],     ah, bh0);
                MMA_BF16(of[2 * dtp + 1], ah, bh1);
                MMA_BF16(of[2 * dtp],     ah, bl0);
                MMA_BF16(of[2 * dtp + 1], ah, bl1);
                MMA_BF16(of[2 * dtp],     al, bh0);
                MMA_BF16(of[2 * dtp + 1], al, bh1);
            }
        }
    }

    l_lo += __shfl_xor_sync(0xffffffffu, l_lo, 1);
    l_lo += __shfl_xor_sync(0xffffffffu, l_lo, 2);
    l_hi += __shfl_xor_sync(0xffffffffu, l_hi, 1);
    l_hi += __shfl_xor_sync(0xffffffffu, l_hi, 2);
    float il = 1.f / l_lo, ih = 1.f / l_hi;

    const int b    = bh >> 3;
    const int hh2  = bh & 7;
    const int s_lo = qt * 64 + w * 16 + (lane >> 2);
    const int s_hi = s_lo + 8;
    const int dcol = hh2 * HD + 2 * (lane & 3);

#pragma unroll
    for (int dt = 0; dt < 8; dt++) {
        int d = dcol + dt * 8;
        if (s_lo < SS) {
            float v0 = of[dt][0] * il, v1 = of[dt][1] * il;
            float h0 = __bfloat162float(__float2bfloat16(v0));
            float h1 = __bfloat162float(__float2bfloat16(v1));
            size_t idx = (size_t)(b * SS + s_lo) * DD + d;
            *(uint32_t*)(Oh + idx) = pk2(v0, v1);
            *(uint32_t*)(Ol + idx) = pk2(v0 - h0, v1 - h1);
        }
        if (s_hi < SS) {
            float v2 = of[dt][2] * ih, v3 = of[dt][3] * ih;
            float h2 = __bfloat162float(__float2bfloat16(v2));
            float h3 = __bfloat162float(__float2bfloat16(v3));
            size_t idx = (size_t)(b * SS + s_hi) * DD + d;
            *(uint32_t*)(Oh + idx) = pk2(v2, v3);
            *(uint32_t*)(Ol + idx) = pk2(v2 - h2, v3 - h3);
        }
    }
}

// ---------------------------------------------------------------------------
// Tensor-core GEMM: product-major (reuse distance 4), x4 B-ldmatrix,
// cp.async double-buffered. RESID fp32 or split-bf16 (RSPLIT).
// ---------------------------------------------------------------------------
#define G_ROWB   80
#define G_MAT    10240
#define G_STAGE  40960
#define G_SMEM   81920

template<bool RELU, bool RESID, bool RSPLIT, bool PACKOUT>
__global__ __launch_bounds__(256, 2) void gemm_mma_kernel(
        const __nv_bfloat16* __restrict__ Ah, const __nv_bfloat16* __restrict__ Al,
        const __nv_bfloat16* __restrict__ Wh, const __nv_bfloat16* __restrict__ Wl,
        const float* __restrict__ bias,
        const float* __restrict__ R,
        const __nv_bfloat16* __restrict__ Rh, const __nv_bfloat16* __restrict__ Rl,
        float* __restrict__ Cf,
        __nv_bfloat16* __restrict__ Ch, __nv_bfloat16* __restrict__ Cl,
        int M, int N, int K)
{
    extern __shared__ char dsm[];
    const uint32_t sb = smem_u32(dsm);

    const int tid  = threadIdx.x;
    const int lane = tid & 31;
    const int wid  = tid >> 5;
    const int wm   = (wid & 1) * 64;
    const int wn   = (wid >> 1) * 32;
    const int m0   = blockIdx.y * 128;
    const int n0   = blockIdx.x * 128;

    float acc[4][4][4] = {};

    const int prow0 = tid >> 2;
    const int prow1 = prow0 + 64;
    const int pc8   = (tid & 3) * 8;
    const uint32_t pdst0 = (uint32_t)(prow0 * G_ROWB + pc8 * 2);
    const uint32_t pdst1 = (uint32_t)(prow1 * G_ROWB + pc8 * 2);

    const int arow  = lane & 15;
    const int acsel = (lane >> 4) * 8;

    const int nchunk = K >> 5;

    auto prefetch = [&](int kc, int st) {
        const int k0 = kc << 5;
        const uint32_t s0 = sb + st * G_STAGE;
        cp16(s0 + 0*G_MAT + pdst0, Ah + (size_t)(m0 + prow0) * K + k0 + pc8);
        cp16(s0 + 0*G_MAT + pdst1, Ah + (size_t)(m0 + prow1) * K + k0 + pc8);
        cp16(s0 + 1*G_MAT + pdst0, Al + (size_t)(m0 + prow0) * K + k0 + pc8);
        cp16(s0 + 1*G_MAT + pdst1, Al + (size_t)(m0 + prow1) * K + k0 + pc8);
        cp16(s0 + 2*G_MAT + pdst0, Wh + (size_t)(n0 + prow0) * K + k0 + pc8);
        cp16(s0 + 2*G_MAT + pdst1, Wh + (size_t)(n0 + prow1) * K + k0 + pc8);
        cp16(s0 + 3*G_MAT + pdst0, Wl + (size_t)(n0 + prow0) * K + k0 + pc8);
        cp16(s0 + 3*G_MAT + pdst1, Wl + (size_t)(n0 + prow1) * K + k0 + pc8);
    };

    prefetch(0, 0);
    CP_COMMIT();

    for (int kc = 0; kc < nchunk; kc++) {
        const int st = kc & 1;
        if (kc + 1 < nchunk) {
            prefetch(kc + 1, st ^ 1);
            CP_COMMIT();
            CP_WAIT1();
        } else {
            CP_WAIT0();
        }
        __syncthreads();

        const uint32_t s0 = sb + st * G_STAGE;
#pragma unroll
        for (int ks = 0; ks < 2; ks++) {
            const int kcol = ks * 16;

            uint32_t bh[4][2], bl[4][2];
#pragma unroll
            for (int np = 0; np < 2; np++) {
                uint32_t r4b[4];
                uint32_t r = (uint32_t)((wn + np * 16 + arow) * G_ROWB + (kcol + acsel) * 2);
                LDMATRIX_X4(r4b, s0 + 2*G_MAT + r);
                bh[np*2    ][0] = r4b[0]; bh[np*2    ][1] = r4b[2];
                bh[np*2 + 1][0] = r4b[1]; bh[np*2 + 1][1] = r4b[3];
                LDMATRIX_X4(r4b, s0 + 3*G_MAT + r);
                bl[np*2    ][0] = r4b[0]; bl[np*2    ][1] = r4b[2];
                bl[np*2 + 1][0] = r4b[1]; bl[np*2 + 1][1] = r4b[3];
            }
#pragma unroll
            for (int mt = 0; mt < 4; mt++) {
                uint32_t ahf[4], alf[4];
                uint32_t r = (uint32_t)((wm + mt * 16 + arow) * G_ROWB + (kcol + acsel) * 2);
                LDMATRIX_X4(ahf, s0 + 0*G_MAT + r);
                LDMATRIX_X4(alf, s0 + 1*G_MAT + r);
#pragma unroll
                for (int nt = 0; nt < 4; nt++) MMA_BF16(acc[mt][nt], ahf, bh[nt]);
#pragma unroll
                for (int nt = 0; nt < 4; nt++) MMA_BF16(acc[mt][nt], ahf, bl[nt]);
#pragma unroll
                for (int nt = 0; nt < 4; nt++) MMA_BF16(acc[mt][nt], alf, bh[nt]);
            }
        }
        __syncthreads();
    }

    const int r4 = lane >> 2;
    const int c2 = (lane & 3) * 2;
#pragma unroll
    for (int mt = 0; mt < 4; mt++) {
#pragma unroll
        for (int nt = 0; nt < 4; nt++) {
#pragma unroll
            for (int e = 0; e < 4; e++) {
                int mg = m0 + wm + mt * 16 + r4 + (e >> 1) * 8;
                int ng = n0 + wn + nt * 8 + c2 + (e & 1);
                float v = acc[mt][nt][e] + bias[ng];
                if (RELU)  v = fmaxf(v, 0.f);
                if (RESID) {
                    if (RSPLIT)
                        v += __bfloat162float(Rh[(size_t)mg * N + ng])
                           + __bfloat162float(Rl[(size_t)mg * N + ng]);
                    else
                        v += R[(size_t)mg * N + ng];
                }
                if (PACKOUT) {
                    __nv_bfloat16 hb = __float2bfloat16(v);
                    Ch[(size_t)mg * N + ng] = hb;
                    Cl[(size_t)mg * N + ng] = __float2bfloat16(v - __bfloat162float(hb));
                } else {
                    Cf[(size_t)mg * N + ng] = v;
                }
            }
        }
    }
}

// ---------------------------------------------------------------------------
// LayerNorm; PACK=1 writes only the split-bf16 pair, PACK=0 only fp32.
// ---------------------------------------------------------------------------
template<bool PACK>
__global__ void ln_kernel(const float* __restrict__ x,
                          const float* __restrict__ w,
                          const float* __restrict__ b,
                          float* __restrict__ y,
                          __nv_bfloat16* __restrict__ yh,
                          __nv_bfloat16* __restrict__ yl)
{
    int r = blockIdx.x;
    int t = threadIdx.x;
    const float* xr = x + (size_t)r * DD;

    float v0 = xr[t], v1 = xr[t + 256];
    float s  = v0 + v1;
    float sq = v0 * v0 + v1 * v1;

#pragma unroll
    for (int off = 16; off; off >>= 1) {
        s  += __shfl_xor_sync(0xffffffffu, s,  off);
        sq += __shfl_xor_sync(0xffffffffu, sq, off);
    }
    __shared__ float sw[8], sqw[8];
    if ((t & 31) == 0) { sw[t >> 5] = s; sqw[t >> 5] = sq; }
    __syncthreads();
    s  = sw[0] + sw[1] + sw[2] + sw[3] + sw[4] + sw[5] + sw[6] + sw[7];
    sq = sqw[0] + sqw[1] + sqw[2] + sqw[3] + sqw[4] + sqw[5] + sqw[6] + sqw[7];

    float mean = s * (1.f / DD);
    float var  = sq * (1.f / DD) - mean * mean;
    float inv  = rsqrtf(var + 1e-5f);

    float r0 = (v0 - mean) * inv * w[t]       + b[t];
    float r1 = (v1 - mean) * inv * w[t + 256] + b[t + 256];
    if (!PACK) {
        float* yr = y + (size_t)r * DD;
        yr[t]       = r0;
        yr[t + 256] = r1;
    } else {
        size_t base = (size_t)r * DD;
        __nv_bfloat16 h0 = __float2bfloat16(r0);
        __nv_bfloat16 h1 = __float2bfloat16(r1);
        yh[base + t]       = h0;
        yh[base + t + 256] = h1;
        yl[base + t]       = __float2bfloat16(r0 - __bfloat162float(h0));
        yl[base + t + 256] = __float2bfloat16(r1 - __bfloat162float(h1));
    }
}

// ---------------------------------------------------------------------------
// Host launcher
// ---------------------------------------------------------------------------
extern "C" void kernel_launch(void* const* d_in, const int* in_sizes, int n_in,
                              void* d_out, int out_size)
{
    const int*   x    = (const int*)  d_in[0];
    const float* emb  = (const float*)d_in[1];
    const float* pe   = (const float*)d_in[2];
    const float* Wq   = (const float*)d_in[3];
    const float* Wk   = (const float*)d_in[4];
    const float* Wv   = (const float*)d_in[5];
    const float* Wo   = (const float*)d_in[6];
    const float* bo   = (const float*)d_in[7];
    const float* ln1w = (const float*)d_in[8];
    const float* ln1b = (const float*)d_in[9];
    const float* W1   = (const float*)d_in[10];
    const float* b1   = (const float*)d_in[11];
    const float* W2   = (const float*)d_in[12];
    const float* b2   = (const float*)d_in[13];
    const float* ln2w = (const float*)d_in[14];
    const float* ln2b = (const float*)d_in[15];
    float* out = (float*)d_out;

    float *h, *t;
    __nv_bfloat16 *qh, *kh, *vh, *vl;
    __nv_bfloat16 *oh, *ol, *n1h, *n1l, *ffh, *ffl;
    __nv_bfloat16 *woh, *wol, *w1h, *w1l, *w2h, *w2l;
    cudaGetSymbolAddress((void**)&h,   g_h);
    cudaGetSymbolAddress((void**)&t,   g_t);
    cudaGetSymbolAddress((void**)&qh,  g_qh);
    cudaGetSymbolAddress((void**)&kh,  g_kh);
    cudaGetSymbolAddress((void**)&vh,  g_vh);
    cudaGetSymbolAddress((void**)&vl,  g_vl);
    cudaGetSymbolAddress((void**)&oh,  g_oh);
    cudaGetSymbolAddress((void**)&ol,  g_ol);
    cudaGetSymbolAddress((void**)&n1h, g_n1h);
    cudaGetSymbolAddress((void**)&n1l, g_n1l);
    cudaGetSymbolAddress((void**)&ffh, g_ffh);
    cudaGetSymbolAddress((void**)&ffl, g_ffl);
    cudaGetSymbolAddress((void**)&woh, g_woh);
    cudaGetSymbolAddress((void**)&wol, g_wol);
    cudaGetSymbolAddress((void**)&w1h, g_w1h);
    cudaGetSymbolAddress((void**)&w1l, g_w1l);
    cudaGetSymbolAddress((void**)&w2h, g_w2h);
    cudaGetSymbolAddress((void**)&w2l, g_w2l);

    cudaFuncSetAttribute(gemm_mma_kernel<false, true,  false, false>,
                         cudaFuncAttributeMaxDynamicSharedMemorySize, G_SMEM);
    cudaFuncSetAttribute(gemm_mma_kernel<false, true,  true,  false>,
                         cudaFuncAttributeMaxDynamicSharedMemorySize, G_SMEM);
    cudaFuncSetAttribute(gemm_mma_kernel<true,  false, false, true>,
                         cudaFuncAttributeMaxDynamicSharedMemorySize, G_SMEM);
    cudaFuncSetAttribute(attn3_kernel,
                         cudaFuncAttributeMaxDynamicSharedMemorySize, AT_SMEM);

    // Launch order keeps attn3 (layer 0) at the profiled index 3.
    pack_all_kernel<<<(PTOT + 255) / 256, 256>>>(Wo, W1, W2,               // 0
                                                 woh, wol, w1h, w1l, w2h, w2l);
    embed_kernel<<<MM * DD / 256, 256>>>(x, emb, pe, h);                   // 1

    for (int l = 0; l < LL; l++) {
        qkv2_kernel<<<dim3(BB * HH, SP / 32, 2), 256>>>(                   // 2 (l=0)
            h, Wq + l * HD * HD, Wk + l * HD * HD, Wv + l * HD * HD,
            qh, kh, vh, vl);

        attn3_kernel<<<dim3(BB * HH, SP / 64), 128, AT_SMEM>>>(            // 3 (l=0) <- profiled
            qh, kh, vh, vl, oh, ol);

        // t = o @ Wo^T + bo + h   (fp32 residual, fp32 out)
        gemm_mma_kernel<false, true, false, false><<<dim3(DD / 128, MM / 128), 256, G_SMEM>>>(
            oh, ol, woh + (size_t)l * DD * DD, wol + (size_t)l * DD * DD,
            bo + l * DD, h, nullptr, nullptr, t, nullptr, nullptr, MM, DD, DD);

        ln_kernel<true><<<MM, 256>>>(t, ln1w + l * DD, ln1b + l * DD,
                                     nullptr, n1h, n1l);

        // ff = relu(n1 @ W1^T + b1)  (split-bf16 out)
        gemm_mma_kernel<true, false, false, true><<<dim3(FF / 128, MM / 128), 256, G_SMEM>>>(
            n1h, n1l, w1h + (size_t)l * FF * DD, w1l + (size_t)l * FF * DD,
            b1 + l * FF, nullptr, nullptr, nullptr, nullptr, ffh, ffl, MM, FF, DD);

        // t = ff @ W2^T + b2 + n1  (split residual, fp32 out)
        gemm_mma_kernel<false, true, true, false><<<dim3(DD / 128, MM / 128), 256, G_SMEM>>>(
            ffh, ffl, w2h + (size_t)l * DD * FF, w2l + (size_t)l * DD * FF,
            b2 + l * DD, nullptr, n1h, n1l, t, nullptr, nullptr, MM, DD, FF);

        float* dst = (l == LL - 1) ? out : h;
        ln_kernel<false><<<MM, 256>>>(t, ln2w + l * DD, ln2b + l * DD,
                                      dst, nullptr, nullptr);
    }
}